// round 1
// baseline (speedup 1.0000x reference)
#include <cuda_runtime.h>

// Shapes: probs (2,2,32,512,512) fp32, gt_mask (2,32,512,512) int32.
// Output: scalar fp32 = mean over all of (probs - onehot(target))^2,
// target = (gt == 1) since ignore_index=2 -> 0 and clamp [0,1].

constexpr int DHW      = 32 * 512 * 512;   // 8388608 = 2^23
constexpr int NGT      = 2 * DHW;          // 16777216
constexpr int VEC      = NGT / 4;          // 4194304 int4/float4 groups per (b, spatial)
constexpr int DHW4     = DHW / 4;          // 2097152 = 2^21
constexpr int BLOCKS   = 1024;
constexpr int THREADS  = 256;

__device__ float g_partials[BLOCKS];

__device__ __forceinline__ float warp_sum(float v) {
    #pragma unroll
    for (int o = 16; o > 0; o >>= 1)
        v += __shfl_xor_sync(0xFFFFFFFFu, v, o);
    return v;
}

__global__ __launch_bounds__(THREADS) void mse_partial_kernel(
    const float* __restrict__ probs, const int* __restrict__ gt)
{
    const float4* __restrict__ p4 = reinterpret_cast<const float4*>(probs);
    const int4*   __restrict__ g4 = reinterpret_cast<const int4*>(gt);

    float acc = 0.0f;
    const int stride = gridDim.x * blockDim.x;
    for (int idx = blockIdx.x * blockDim.x + threadIdx.x; idx < VEC; idx += stride) {
        int4 g = g4[idx];
        int b = idx >> 21;            // DHW4 = 2^21
        int r = idx & (DHW4 - 1);
        // probs layout (B, C, D, H, W): channel stride = DHW
        float4 p0 = p4[(size_t)(2 * b    ) * DHW4 + r];  // c = 0
        float4 p1 = p4[(size_t)(2 * b + 1) * DHW4 + r];  // c = 1

        // onehot: oh0 = (gt != 1), oh1 = (gt == 1)
        float d;
        d = p0.x - (float)(g.x != 1); acc = fmaf(d, d, acc);
        d = p1.x - (float)(g.x == 1); acc = fmaf(d, d, acc);
        d = p0.y - (float)(g.y != 1); acc = fmaf(d, d, acc);
        d = p1.y - (float)(g.y == 1); acc = fmaf(d, d, acc);
        d = p0.z - (float)(g.z != 1); acc = fmaf(d, d, acc);
        d = p1.z - (float)(g.z == 1); acc = fmaf(d, d, acc);
        d = p0.w - (float)(g.w != 1); acc = fmaf(d, d, acc);
        d = p1.w - (float)(g.w == 1); acc = fmaf(d, d, acc);
    }

    // block reduction: warp shuffles -> smem -> first warp
    __shared__ float smem[THREADS / 32];
    acc = warp_sum(acc);
    int lane = threadIdx.x & 31;
    int wid  = threadIdx.x >> 5;
    if (lane == 0) smem[wid] = acc;
    __syncthreads();
    if (wid == 0) {
        float v = (lane < THREADS / 32) ? smem[lane] : 0.0f;
        v = warp_sum(v);
        if (lane == 0) g_partials[blockIdx.x] = v;
    }
}

__global__ __launch_bounds__(1024) void mse_final_kernel(float* __restrict__ out)
{
    // BLOCKS == 1024 partials, one per thread
    float v = g_partials[threadIdx.x];
    __shared__ float smem[32];
    v = warp_sum(v);
    int lane = threadIdx.x & 31;
    int wid  = threadIdx.x >> 5;
    if (lane == 0) smem[wid] = v;
    __syncthreads();
    if (wid == 0) {
        float t = (lane < 32) ? smem[lane] : 0.0f;
        t = warp_sum(t);
        if (lane == 0)
            out[0] = t * (1.0f / 33554432.0f);  // 1 / (B*C*D*H*W)
    }
}

extern "C" void kernel_launch(void* const* d_in, const int* in_sizes, int n_in,
                              void* d_out, int out_size)
{
    const float* probs = (const float*)d_in[0];
    const int*   gt    = (const int*)d_in[1];
    float*       out   = (float*)d_out;

    mse_partial_kernel<<<BLOCKS, THREADS>>>(probs, gt);
    mse_final_kernel<<<1, 1024>>>(out);
}